// round 1
// baseline (speedup 1.0000x reference)
#include <cuda_runtime.h>

namespace {

constexpr int SEQ = 2048;   // sequence length (n_qry == n_tok)
constexpr int HD  = 64;     // head dim
constexpr int NBH = 32;     // B*H = 2*16
constexpr int BQ  = 64;     // q rows per block
constexpr int BK  = 64;     // k cols per tile
constexpr int NTH = 256;    // threads per block (16x16 thread grid, 4x4 regs each)
constexpr int VSTR = 68;    // padded V row stride (floats) to avoid STS conflicts

__global__ __launch_bounds__(NTH, 1)
void fa_fp32_kernel(const float* __restrict__ Qg_,
                    const float* __restrict__ Kg_,
                    const float* __restrict__ Vg_,
                    float* __restrict__ Og_)
{
    extern __shared__ float sm[];
    float* Qs = sm;                 // [d][q]  64x64, transposed, pre-scaled
    float* Ks = Qs + BQ * HD;       // [d][c]  64x64, transposed
    float* Ps = Ks + BK * HD;       // [q][k]  64x64, row-major
    float* Vs = Ps + BQ * BK;       // [k][dd] 64x68 (padded)

    const int tid = threadIdx.x;
    const int tx  = tid & 15;       // S-tile column group / O d-col group
    const int ty  = tid >> 4;       // S-tile row group (q rows)
    // reverse order: heaviest (most k-tiles) q-blocks launch first
    const int qt  = (int)gridDim.x - 1 - (int)blockIdx.x;
    const int bh  = blockIdx.y;

    const float* Qg = Qg_ + ((size_t)bh * SEQ + (size_t)qt * BQ) * HD;
    const float* Kg = Kg_ + (size_t)bh * SEQ * HD;
    const float* Vg = Vg_ + (size_t)bh * SEQ * HD;
    float*       Og = Og_ + ((size_t)bh * SEQ + (size_t)qt * BQ) * HD;

    // ---- Load Q tile transposed into Qs[d][q], folded scale 1/sqrt(64) ----
    #pragma unroll
    for (int u = 0; u < (BQ * HD / 4) / NTH; ++u) {
        int i  = u * NTH + tid;
        int q  = i & 63;
        int dg = i >> 6;            // 0..15, group of 4 d's
        float4 v = reinterpret_cast<const float4*>(Qg + (size_t)q * HD)[dg];
        Qs[(4 * dg + 0) * BQ + q] = v.x * 0.125f;
        Qs[(4 * dg + 1) * BQ + q] = v.y * 0.125f;
        Qs[(4 * dg + 2) * BQ + q] = v.z * 0.125f;
        Qs[(4 * dg + 3) * BQ + q] = v.w * 0.125f;
    }

    float o[4][4] = {};
    float m[4], l[4];
    #pragma unroll
    for (int i = 0; i < 4; ++i) { m[i] = -1e30f; l[i] = 0.0f; }

    for (int kb = 0; kb <= qt; ++kb) {
        __syncthreads();   // prev PV done (and Q visible on first iter)

        // ---- Load K tile transposed -> Ks[d][c]; V tile row-major -> Vs ----
        #pragma unroll
        for (int u = 0; u < 4; ++u) {
            int i  = u * NTH + tid;
            int c  = i & 63;
            int dg = i >> 6;
            const float* krow = Kg + (size_t)(kb * BK + c) * HD;
            float4 kv = reinterpret_cast<const float4*>(krow)[dg];
            Ks[(4 * dg + 0) * BK + c] = kv.x;
            Ks[(4 * dg + 1) * BK + c] = kv.y;
            Ks[(4 * dg + 2) * BK + c] = kv.z;
            Ks[(4 * dg + 3) * BK + c] = kv.w;
            const float* vrow = Vg + (size_t)(kb * BK + c) * HD;
            float4 vv = reinterpret_cast<const float4*>(vrow)[dg];
            *reinterpret_cast<float4*>(Vs + c * VSTR + 4 * dg) = vv;
        }
        __syncthreads();

        // ---- S = (Q*scale) @ K^T : 4x4 register tile per thread ----
        float acc[4][4] = {};
        #pragma unroll 8
        for (int d = 0; d < HD; ++d) {
            float4 qv = *reinterpret_cast<const float4*>(Qs + d * BQ + 4 * ty);
            float4 kv = *reinterpret_cast<const float4*>(Ks + d * BK + 4 * tx);
            float qa[4] = {qv.x, qv.y, qv.z, qv.w};
            float ka[4] = {kv.x, kv.y, kv.z, kv.w};
            #pragma unroll
            for (int i = 0; i < 4; ++i)
                #pragma unroll
                for (int j = 0; j < 4; ++j)
                    acc[i][j] = fmaf(qa[i], ka[j], acc[i][j]);
        }

        // ---- Causal mask: only on the diagonal tile ----
        if (kb == qt) {
            #pragma unroll
            for (int i = 0; i < 4; ++i)
                #pragma unroll
                for (int j = 0; j < 4; ++j)
                    if (4 * tx + j > 4 * ty + i) acc[i][j] = -1e30f;
        }

        // ---- Online softmax update (row stats across 16 lanes) ----
        #pragma unroll
        for (int i = 0; i < 4; ++i) {
            float mt = fmaxf(fmaxf(acc[i][0], acc[i][1]),
                             fmaxf(acc[i][2], acc[i][3]));
            #pragma unroll
            for (int off = 8; off; off >>= 1)
                mt = fmaxf(mt, __shfl_xor_sync(0xffffffffu, mt, off));
            float mn   = fmaxf(m[i], mt);
            float corr = __expf(m[i] - mn);   // first tile: exp(-1e30-x) -> 0
            m[i] = mn;
            float rs = 0.0f;
            #pragma unroll
            for (int j = 0; j < 4; ++j) {
                acc[i][j] = __expf(acc[i][j] - mn);  // masked -> exp(-1e30)=0
                rs += acc[i][j];
            }
            #pragma unroll
            for (int off = 8; off; off >>= 1)
                rs += __shfl_xor_sync(0xffffffffu, rs, off);
            l[i] = l[i] * corr + rs;
            #pragma unroll
            for (int j = 0; j < 4; ++j) o[i][j] *= corr;
            *reinterpret_cast<float4*>(Ps + (4 * ty + i) * BK + 4 * tx) =
                make_float4(acc[i][0], acc[i][1], acc[i][2], acc[i][3]);
        }
        // P rows (4*ty+i) are written and read entirely within this warp
        __syncwarp();

        // ---- O += P @ V ----
        #pragma unroll 8
        for (int k = 0; k < BK; ++k) {
            float4 vv = *reinterpret_cast<const float4*>(Vs + k * VSTR + 4 * tx);
            float va[4] = {vv.x, vv.y, vv.z, vv.w};
            #pragma unroll
            for (int i = 0; i < 4; ++i) {
                float p = Ps[(4 * ty + i) * BK + k];
                #pragma unroll
                for (int j = 0; j < 4; ++j)
                    o[i][j] = fmaf(p, va[j], o[i][j]);
            }
        }
    }

    // ---- Epilogue: normalize and store ----
    #pragma unroll
    for (int i = 0; i < 4; ++i) {
        float rl = 1.0f / l[i];
        float4 out = make_float4(o[i][0] * rl, o[i][1] * rl,
                                 o[i][2] * rl, o[i][3] * rl);
        *reinterpret_cast<float4*>(Og + (size_t)(4 * ty + i) * HD + 4 * tx) = out;
    }
}

constexpr int SMEM_BYTES = (BQ * HD + BK * HD + BQ * BK + BK * VSTR) * 4; // 66560

} // namespace

extern "C" void kernel_launch(void* const* d_in, const int* in_sizes, int n_in,
                              void* d_out, int out_size)
{
    const float* Q = (const float*)d_in[0];
    const float* K = (const float*)d_in[1];
    const float* V = (const float*)d_in[2];
    float*       O = (float*)d_out;

    cudaFuncSetAttribute(fa_fp32_kernel,
                         cudaFuncAttributeMaxDynamicSharedMemorySize, SMEM_BYTES);

    dim3 grid(SEQ / BQ, NBH);   // 32 q-tiles x 32 (b,h)
    fa_fp32_kernel<<<grid, NTH, SMEM_BYTES>>>(Q, K, V, O);
}

// round 3
// speedup vs baseline: 3.4642x; 3.4642x over previous
#include <cuda_runtime.h>
#include <cuda_bf16.h>
#include <cstdint>

namespace {

constexpr int SEQ = 2048, HD = 64, BQ = 64, BK = 64, NTH = 128;
constexpr int QT_N = SEQ / BQ;   // 32 q tiles
constexpr int NBH  = 32;         // B*H

// smem regions (bf16 tiles, 64 rows x 128B, XOR-swizzled)
constexpr uint32_t QHI = 0,     QLO = 8192,  KHI = 16384,
                   KLO = 24576, VHI = 32768, VLO = 40960;
constexpr uint32_t SMEM_BYTES = 49152;

__device__ __forceinline__ uint32_t swz(uint32_t x) { return x ^ ((x >> 3) & 0x70u); }

__device__ __forceinline__ uint32_t s2u(const void* p) {
    uint32_t a;
    asm("{ .reg .u64 t; cvta.to.shared.u64 t, %1; cvt.u32.u64 %0, t; }" : "=r"(a) : "l"(p));
    return a;
}
__device__ __forceinline__ float ex2(float x) {
    float r;
    asm("ex2.approx.ftz.f32 %0, %1;" : "=f"(r) : "f"(x));
    return r;
}
__device__ __forceinline__ void ldsm4(uint32_t& r0, uint32_t& r1, uint32_t& r2, uint32_t& r3,
                                      uint32_t a) {
    asm volatile("ldmatrix.sync.aligned.m8n8.x4.shared.b16 {%0,%1,%2,%3}, [%4];"
                 : "=r"(r0), "=r"(r1), "=r"(r2), "=r"(r3) : "r"(a));
}
__device__ __forceinline__ void ldsm4t(uint32_t& r0, uint32_t& r1, uint32_t& r2, uint32_t& r3,
                                       uint32_t a) {
    asm volatile("ldmatrix.sync.aligned.m8n8.x4.trans.shared.b16 {%0,%1,%2,%3}, [%4];"
                 : "=r"(r0), "=r"(r1), "=r"(r2), "=r"(r3) : "r"(a));
}
__device__ __forceinline__ void mma(float (&d)[4], const uint32_t a0, const uint32_t a1,
                                    const uint32_t a2, const uint32_t a3,
                                    const uint32_t b0, const uint32_t b1) {
    asm volatile(
        "mma.sync.aligned.m16n8k16.row.col.f32.bf16.bf16.f32 "
        "{%0,%1,%2,%3}, {%4,%5,%6,%7}, {%8,%9}, {%0,%1,%2,%3};"
        : "+f"(d[0]), "+f"(d[1]), "+f"(d[2]), "+f"(d[3])
        : "r"(a0), "r"(a1), "r"(a2), "r"(a3), "r"(b0), "r"(b1));
}
// fp32 pair -> packed bf16x2 hi + lo residual (low half = first element)
__device__ __forceinline__ void split_pair(float a, float b, uint32_t& hi, uint32_t& lo) {
    __nv_bfloat162 h = __floats2bfloat162_rn(a, b);
    float2 hf = __bfloat1622float2(h);
    __nv_bfloat162 l = __floats2bfloat162_rn(a - hf.x, b - hf.y);
    hi = *reinterpret_cast<uint32_t*>(&h);
    lo = *reinterpret_cast<uint32_t*>(&l);
}

__global__ __launch_bounds__(NTH, 3)
void fa_hmma_kernel(const float* __restrict__ Qg_, const float* __restrict__ Kg_,
                    const float* __restrict__ Vg_, float* __restrict__ Og_)
{
    extern __shared__ __align__(1024) char smp[];
    const uint32_t sb = s2u(smp);

    const int tid  = threadIdx.x;
    const int lane = tid & 31, warp = tid >> 5;
    const int quad = lane >> 2, qp = lane & 3;
    const int qt = (QT_N - 1) - (int)blockIdx.x;   // heaviest first
    const int bh = blockIdx.y;

    const float* Qg = Qg_ + ((size_t)bh * SEQ + (size_t)qt * BQ) * HD;
    const float* Kg = Kg_ + (size_t)bh * SEQ * HD;
    const float* Vg = Vg_ + (size_t)bh * SEQ * HD;
    float*       Og = Og_ + ((size_t)bh * SEQ + (size_t)qt * BQ) * HD;

    // ---- load Q once: fold scale*log2(e), split hi/lo bf16 ----
    constexpr float QSC = 0.125f * 1.44269504f;
    #pragma unroll
    for (int it = 0; it < 8; ++it) {
        int i = it * NTH + tid;
        int r = i >> 4, dg = i & 15;
        float4 v = reinterpret_cast<const float4*>(Qg)[i];
        uint32_t h0, l0, h1, l1;
        split_pair(v.x * QSC, v.y * QSC, h0, l0);
        split_pair(v.z * QSC, v.w * QSC, h1, l1);
        uint32_t off = (uint32_t)r * 128u + (uint32_t)dg * 8u;
        *(uint32_t*)(smp + QHI + swz(off))     = h0;
        *(uint32_t*)(smp + QHI + swz(off + 4)) = h1;
        *(uint32_t*)(smp + QLO + swz(off))     = l0;
        *(uint32_t*)(smp + QLO + swz(off + 4)) = l1;
    }

    // per-lane ldmatrix address components
    const uint32_t rowA  = 16u * warp + (lane & 7) + 8u * ((lane >> 3) & 1);
    const uint32_t kprtA = ((uint32_t)lane >> 4) * 16u;             // A: k-halves
    const uint32_t nB    = 8u * ((uint32_t)lane >> 4) + (lane & 7); // B(S): n within pair
    const uint32_t kprtB = ((lane >> 3) & 1) * 16u;
    const uint32_t rowV  = (uint32_t)(lane & 15);                   // B(PV): k rows
    const uint32_t colV  = 16u * ((uint32_t)lane >> 4);

    float o[8][4] = {};
    float m0 = -1e30f, m1 = -1e30f, l0 = 0.0f, l1 = 0.0f;
    const int qr0 = 16 * warp + quad, qr1 = qr0 + 8;

    for (int kb = 0; kb <= qt; ++kb) {
        if (kb) __syncthreads();   // smem K/V reads from previous tile done

        // ---- load K,V tile; split hi/lo bf16 into smem ----
        const float* Kt = Kg + (size_t)kb * BK * HD;
        const float* Vt = Vg + (size_t)kb * BK * HD;
        #pragma unroll
        for (int it = 0; it < 8; ++it) {
            int i = it * NTH + tid;
            int r = i >> 4, dg = i & 15;
            uint32_t off = (uint32_t)r * 128u + (uint32_t)dg * 8u;
            uint32_t so0 = swz(off), so1 = swz(off + 4);
            float4 kv = reinterpret_cast<const float4*>(Kt)[i];
            uint32_t h0, lo0, h1, lo1;
            split_pair(kv.x, kv.y, h0, lo0);
            split_pair(kv.z, kv.w, h1, lo1);
            *(uint32_t*)(smp + KHI + so0) = h0;
            *(uint32_t*)(smp + KHI + so1) = h1;
            *(uint32_t*)(smp + KLO + so0) = lo0;
            *(uint32_t*)(smp + KLO + so1) = lo1;
            float4 vv = reinterpret_cast<const float4*>(Vt)[i];
            split_pair(vv.x, vv.y, h0, lo0);
            split_pair(vv.z, vv.w, h1, lo1);
            *(uint32_t*)(smp + VHI + so0) = h0;
            *(uint32_t*)(smp + VHI + so1) = h1;
            *(uint32_t*)(smp + VLO + so0) = lo0;
            *(uint32_t*)(smp + VLO + so1) = lo1;
        }
        __syncthreads();

        // ---- S = Q K^T (3 bf16 passes) ----
        float s[8][4] = {};
        #pragma unroll
        for (int ks = 0; ks < 4; ++ks) {
            uint32_t offA = rowA * 128u + kprtA + (uint32_t)ks * 32u;
            uint32_t ah0, ah1, ah2, ah3, al0, al1, al2, al3;
            ldsm4(ah0, ah1, ah2, ah3, sb + QHI + swz(offA));
            ldsm4(al0, al1, al2, al3, sb + QLO + swz(offA));
            #pragma unroll
            for (int p = 0; p < 4; ++p) {
                uint32_t offB = (16u * p + nB) * 128u + kprtB + (uint32_t)ks * 32u;
                uint32_t bh0, bh1, bh2, bh3, bl0, bl1, bl2, bl3;
                ldsm4(bh0, bh1, bh2, bh3, sb + KHI + swz(offB));
                ldsm4(bl0, bl1, bl2, bl3, sb + KLO + swz(offB));
                mma(s[2*p],   ah0, ah1, ah2, ah3, bh0, bh1);
                mma(s[2*p+1], ah0, ah1, ah2, ah3, bh2, bh3);
                mma(s[2*p],   al0, al1, al2, al3, bh0, bh1);
                mma(s[2*p+1], al0, al1, al2, al3, bh2, bh3);
                mma(s[2*p],   ah0, ah1, ah2, ah3, bl0, bl1);
                mma(s[2*p+1], ah0, ah1, ah2, ah3, bl2, bl3);
            }
        }

        // ---- causal mask (diagonal tile only) ----
        if (kb == qt) {
            #pragma unroll
            for (int nt = 0; nt < 8; ++nt) {
                int c0 = 8 * nt + 2 * qp;
                if (c0 > qr0)     s[nt][0] = -1e30f;
                if (c0 + 1 > qr0) s[nt][1] = -1e30f;
                if (c0 > qr1)     s[nt][2] = -1e30f;
                if (c0 + 1 > qr1) s[nt][3] = -1e30f;
            }
        }

        // ---- online softmax (base-2 domain; log2e folded into Q) ----
        float mt0 = -1e30f, mt1 = -1e30f;
        #pragma unroll
        for (int nt = 0; nt < 8; ++nt) {
            mt0 = fmaxf(mt0, fmaxf(s[nt][0], s[nt][1]));
            mt1 = fmaxf(mt1, fmaxf(s[nt][2], s[nt][3]));
        }
        mt0 = fmaxf(mt0, __shfl_xor_sync(~0u, mt0, 1));
        mt0 = fmaxf(mt0, __shfl_xor_sync(~0u, mt0, 2));
        mt1 = fmaxf(mt1, __shfl_xor_sync(~0u, mt1, 1));
        mt1 = fmaxf(mt1, __shfl_xor_sync(~0u, mt1, 2));
        float mn0 = fmaxf(m0, mt0), mn1 = fmaxf(m1, mt1);
        float c0 = ex2(m0 - mn0), c1 = ex2(m1 - mn1);
        m0 = mn0; m1 = mn1;

        uint32_t phi[16], plo[16];
        float rs0 = 0.f, rs1 = 0.f;
        #pragma unroll
        for (int nt = 0; nt < 8; ++nt) {
            float e0 = ex2(s[nt][0] - mn0), e1 = ex2(s[nt][1] - mn0);
            float e2 = ex2(s[nt][2] - mn1), e3 = ex2(s[nt][3] - mn1);
            rs0 += e0 + e1; rs1 += e2 + e3;
            split_pair(e0, e1, phi[2*nt],     plo[2*nt]);
            split_pair(e2, e3, phi[2*nt + 1], plo[2*nt + 1]);
        }
        rs0 += __shfl_xor_sync(~0u, rs0, 1); rs0 += __shfl_xor_sync(~0u, rs0, 2);
        rs1 += __shfl_xor_sync(~0u, rs1, 1); rs1 += __shfl_xor_sync(~0u, rs1, 2);
        l0 = l0 * c0 + rs0; l1 = l1 * c1 + rs1;

        #pragma unroll
        for (int nt = 0; nt < 8; ++nt) {
            o[nt][0] *= c0; o[nt][1] *= c0;
            o[nt][2] *= c1; o[nt][3] *= c1;
        }

        // ---- O += P V (3 bf16 passes; P frags straight from registers) ----
        #pragma unroll
        for (int ks = 0; ks < 4; ++ks) {
            const uint32_t* ah = phi + 4 * ks;
            const uint32_t* al = plo + 4 * ks;
            #pragma unroll
            for (int p = 0; p < 4; ++p) {
                uint32_t offV = (16u * ks + rowV) * 128u + 32u * p + colV;
                uint32_t bh0, bh1, bh2, bh3, bl0, bl1, bl2, bl3;
                ldsm4t(bh0, bh1, bh2, bh3, sb + VHI + swz(offV));
                ldsm4t(bl0, bl1, bl2, bl3, sb + VLO + swz(offV));
                mma(o[2*p],   ah[0], ah[1], ah[2], ah[3], bh0, bh1);
                mma(o[2*p+1], ah[0], ah[1], ah[2], ah[3], bh2, bh3);
                mma(o[2*p],   al[0], al[1], al[2], al[3], bh0, bh1);
                mma(o[2*p+1], al[0], al[1], al[2], al[3], bh2, bh3);
                mma(o[2*p],   ah[0], ah[1], ah[2], ah[3], bl0, bl1);
                mma(o[2*p+1], ah[0], ah[1], ah[2], ah[3], bl2, bl3);
            }
        }
    }

    // ---- epilogue ----
    float rl0 = 1.0f / l0, rl1 = 1.0f / l1;
    #pragma unroll
    for (int nt = 0; nt < 8; ++nt) {
        int col = 8 * nt + 2 * qp;
        *reinterpret_cast<float2*>(Og + (size_t)qr0 * HD + col) =
            make_float2(o[nt][0] * rl0, o[nt][1] * rl0);
        *reinterpret_cast<float2*>(Og + (size_t)qr1 * HD + col) =
            make_float2(o[nt][2] * rl1, o[nt][3] * rl1);
    }
}

} // namespace

extern "C" void kernel_launch(void* const* d_in, const int* in_sizes, int n_in,
                              void* d_out, int out_size)
{
    const float* Q = (const float*)d_in[0];
    const float* K = (const float*)d_in[1];
    const float* V = (const float*)d_in[2];
    float*       O = (float*)d_out;

    cudaFuncSetAttribute(fa_hmma_kernel,
                         cudaFuncAttributeMaxDynamicSharedMemorySize, SMEM_BYTES);

    dim3 grid(QT_N, NBH);   // 32 q-tiles x 32 (b,h)
    fa_hmma_kernel<<<grid, NTH, SMEM_BYTES>>>(Q, K, V, O);
}

// round 4
// speedup vs baseline: 3.8665x; 1.1161x over previous
#include <cuda_runtime.h>
#include <cuda_bf16.h>
#include <cstdint>

namespace {

constexpr int SEQ = 2048, HD = 64, BQ = 64, BK = 64, NTH = 128;
constexpr int QT_N  = SEQ / BQ;          // 32 q tiles
constexpr int NBH   = 32;                // B*H
constexpr int ELEMS = NBH * SEQ * HD;    // 4,194,304

// pre-split K/V (bf16 hi/lo packed as bf16x2 words), same [bh][s][d] order
__device__ uint32_t g_khi[ELEMS / 2];
__device__ uint32_t g_klo[ELEMS / 2];
__device__ uint32_t g_vhi[ELEMS / 2];
__device__ uint32_t g_vlo[ELEMS / 2];

// smem: two 32KB stages (Khi,Klo,Vhi,Vlo @ 8KB each); Q staged in stage1 pre-loop
constexpr uint32_t STG = 32768;
constexpr uint32_t KHI = 0, KLO = 8192, VHI = 16384, VLO = 24576;
constexpr uint32_t SMEM_BYTES = 2 * STG;   // 64 KB -> 3 CTAs/SM

__device__ __forceinline__ uint32_t swz(uint32_t x) { return x ^ ((x >> 3) & 0x70u); }

__device__ __forceinline__ uint32_t s2u(const void* p) {
    uint32_t a;
    asm("{ .reg .u64 t; cvta.to.shared.u64 t, %1; cvt.u32.u64 %0, t; }" : "=r"(a) : "l"(p));
    return a;
}
__device__ __forceinline__ float ex2(float x) {
    float r;
    asm("ex2.approx.ftz.f32 %0, %1;" : "=f"(r) : "f"(x));
    return r;
}
__device__ __forceinline__ void ldsm4(uint32_t& r0, uint32_t& r1, uint32_t& r2, uint32_t& r3,
                                      uint32_t a) {
    asm volatile("ldmatrix.sync.aligned.m8n8.x4.shared.b16 {%0,%1,%2,%3}, [%4];"
                 : "=r"(r0), "=r"(r1), "=r"(r2), "=r"(r3) : "r"(a));
}
__device__ __forceinline__ void ldsm4t(uint32_t& r0, uint32_t& r1, uint32_t& r2, uint32_t& r3,
                                       uint32_t a) {
    asm volatile("ldmatrix.sync.aligned.m8n8.x4.trans.shared.b16 {%0,%1,%2,%3}, [%4];"
                 : "=r"(r0), "=r"(r1), "=r"(r2), "=r"(r3) : "r"(a));
}
__device__ __forceinline__ void mma(float (&d)[4], const uint32_t a0, const uint32_t a1,
                                    const uint32_t a2, const uint32_t a3,
                                    const uint32_t b0, const uint32_t b1) {
    asm volatile(
        "mma.sync.aligned.m16n8k16.row.col.f32.bf16.bf16.f32 "
        "{%0,%1,%2,%3}, {%4,%5,%6,%7}, {%8,%9}, {%0,%1,%2,%3};"
        : "+f"(d[0]), "+f"(d[1]), "+f"(d[2]), "+f"(d[3])
        : "r"(a0), "r"(a1), "r"(a2), "r"(a3), "r"(b0), "r"(b1));
}
__device__ __forceinline__ void split_pair(float a, float b, uint32_t& hi, uint32_t& lo) {
    __nv_bfloat162 h = __floats2bfloat162_rn(a, b);
    float2 hf = __bfloat1622float2(h);
    __nv_bfloat162 l = __floats2bfloat162_rn(a - hf.x, b - hf.y);
    hi = *reinterpret_cast<uint32_t*>(&h);
    lo = *reinterpret_cast<uint32_t*>(&l);
}
__device__ __forceinline__ void cpa16(uint32_t dst, const void* src) {
    asm volatile("cp.async.cg.shared.global [%0], [%1], 16;" :: "r"(dst), "l"(src) : "memory");
}
#define CP_COMMIT asm volatile("cp.async.commit_group;" ::: "memory")
template <int N>
__device__ __forceinline__ void cp_wait() {
    asm volatile("cp.async.wait_group %0;" :: "n"(N) : "memory");
}

// ---------------- pre-pass: split K,V to bf16 hi/lo ----------------
__global__ __launch_bounds__(256)
void split_kv_kernel(const float4* __restrict__ K, const float4* __restrict__ V)
{
    int i = blockIdx.x * 256 + threadIdx.x;   // one float4 (4 elems) per thread
    float4 k = K[i];
    uint32_t h0, l0, h1, l1;
    split_pair(k.x, k.y, h0, l0);
    split_pair(k.z, k.w, h1, l1);
    g_khi[2*i] = h0; g_khi[2*i+1] = h1;
    g_klo[2*i] = l0; g_klo[2*i+1] = l1;
    float4 v = V[i];
    split_pair(v.x, v.y, h0, l0);
    split_pair(v.z, v.w, h1, l1);
    g_vhi[2*i] = h0; g_vhi[2*i+1] = h1;
    g_vlo[2*i] = l0; g_vlo[2*i+1] = l1;
}

// issue cp.async for one 64x64 K/V hi+lo tile set into stage at smem byte base sdst
__device__ __forceinline__ void issue_tile(uint32_t sdst, int bh, int kb, int tid)
{
    size_t boff = (((size_t)bh * SEQ + (size_t)kb * BK) * HD) * 2;  // byte offset
    const char* kh = (const char*)g_khi + boff;
    const char* kl = (const char*)g_klo + boff;
    const char* vh = (const char*)g_vhi + boff;
    const char* vl = (const char*)g_vlo + boff;
    #pragma unroll
    for (int t = 0; t < 4; ++t) {
        uint32_t i  = (uint32_t)(t * NTH + tid);      // 512 chunks of 16B per array
        uint32_t off = (i >> 3) * 128u + (i & 7u) * 16u;
        uint32_t so  = swz(off);
        cpa16(sdst + KHI + so, kh + off);
        cpa16(sdst + KLO + so, kl + off);
        cpa16(sdst + VHI + so, vh + off);
        cpa16(sdst + VLO + so, vl + off);
    }
}

__global__ __launch_bounds__(NTH, 3)
void fa_hmma_kernel(const float* __restrict__ Qg_, float* __restrict__ Og_)
{
    extern __shared__ __align__(1024) char smp[];
    const uint32_t sb = s2u(smp);

    const int tid  = threadIdx.x;
    const int lane = tid & 31, warp = tid >> 5;
    const int quad = lane >> 2, qp = lane & 3;
    const int qt = (QT_N - 1) - (int)blockIdx.x;   // heaviest first
    const int bh = blockIdx.y;

    const float* Qg = Qg_ + ((size_t)bh * SEQ + (size_t)qt * BQ) * HD;
    float*       Og = Og_ + ((size_t)bh * SEQ + (size_t)qt * BQ) * HD;

    // per-lane ldmatrix address components
    const uint32_t rowA  = 16u * warp + (lane & 7) + 8u * ((lane >> 3) & 1);
    const uint32_t kprtA = ((uint32_t)lane >> 4) * 16u;
    const uint32_t nB    = 8u * ((uint32_t)lane >> 4) + (lane & 7);
    const uint32_t kprtB = ((lane >> 3) & 1) * 16u;
    const uint32_t rowV  = (uint32_t)(lane & 15);
    const uint32_t colV  = 16u * ((uint32_t)lane >> 4);

    // ---- stage Q in stage-1 smem, split, then hoist A-fragments to registers ----
    constexpr float QSC = 0.125f * 1.44269504f;   // fold softmax scale * log2(e)
    {
        char* qtmp = smp + STG;                   // QHI @ +0, QLO @ +8192
        #pragma unroll
        for (int it = 0; it < 8; ++it) {
            int i = it * NTH + tid;
            int r = i >> 4, dg = i & 15;
            float4 v = reinterpret_cast<const float4*>(Qg)[i];
            uint32_t h0, l0, h1, l1;
            split_pair(v.x * QSC, v.y * QSC, h0, l0);
            split_pair(v.z * QSC, v.w * QSC, h1, l1);
            uint32_t off = (uint32_t)r * 128u + (uint32_t)dg * 8u;
            *(uint32_t*)(qtmp + swz(off))            = h0;
            *(uint32_t*)(qtmp + swz(off + 4))        = h1;
            *(uint32_t*)(qtmp + 8192 + swz(off))     = l0;
            *(uint32_t*)(qtmp + 8192 + swz(off + 4)) = l1;
        }
    }
    __syncthreads();

    uint32_t qh[4][4], ql[4][4];
    #pragma unroll
    for (int ks = 0; ks < 4; ++ks) {
        uint32_t offA = rowA * 128u + kprtA + (uint32_t)ks * 32u;
        ldsm4(qh[ks][0], qh[ks][1], qh[ks][2], qh[ks][3], sb + STG + swz(offA));
        ldsm4(ql[ks][0], ql[ks][1], ql[ks][2], ql[ks][3], sb + STG + 8192u + swz(offA));
    }
    __syncthreads();   // stage-1 free for K/V prefetch

    // ---- prime the 2-stage pipeline ----
    issue_tile(sb, bh, 0, tid);
    CP_COMMIT;

    float o[8][4] = {};
    float m0 = -1e30f, m1 = -1e30f, l0 = 0.0f, l1 = 0.0f;
    const int qr0 = 16 * warp + quad, qr1 = qr0 + 8;

    for (int kb = 0; kb <= qt; ++kb) {
        const uint32_t ss = sb + (uint32_t)(kb & 1) * STG;
        if (kb < qt) {
            issue_tile(sb + (uint32_t)((kb + 1) & 1) * STG, bh, kb + 1, tid);
            CP_COMMIT;
            cp_wait<1>();
        } else {
            cp_wait<0>();
        }
        __syncthreads();

        // ---- S = Q K^T (3 bf16 passes) ----
        float s[8][4] = {};
        #pragma unroll
        for (int ks = 0; ks < 4; ++ks) {
            #pragma unroll
            for (int p = 0; p < 4; ++p) {
                uint32_t offB = (16u * p + nB) * 128u + kprtB + (uint32_t)ks * 32u;
                uint32_t bh0, bh1, bh2, bh3, bl0, bl1, bl2, bl3;
                ldsm4(bh0, bh1, bh2, bh3, ss + KHI + swz(offB));
                ldsm4(bl0, bl1, bl2, bl3, ss + KLO + swz(offB));
                mma(s[2*p],   qh[ks][0], qh[ks][1], qh[ks][2], qh[ks][3], bh0, bh1);
                mma(s[2*p+1], qh[ks][0], qh[ks][1], qh[ks][2], qh[ks][3], bh2, bh3);
                mma(s[2*p],   ql[ks][0], ql[ks][1], ql[ks][2], ql[ks][3], bh0, bh1);
                mma(s[2*p+1], ql[ks][0], ql[ks][1], ql[ks][2], ql[ks][3], bh2, bh3);
                mma(s[2*p],   qh[ks][0], qh[ks][1], qh[ks][2], qh[ks][3], bl0, bl1);
                mma(s[2*p+1], qh[ks][0], qh[ks][1], qh[ks][2], qh[ks][3], bl2, bl3);
            }
        }

        // ---- causal mask (diagonal tile only) ----
        if (kb == qt) {
            #pragma unroll
            for (int nt = 0; nt < 8; ++nt) {
                int c0 = 8 * nt + 2 * qp;
                if (c0 > qr0)     s[nt][0] = -1e30f;
                if (c0 + 1 > qr0) s[nt][1] = -1e30f;
                if (c0 > qr1)     s[nt][2] = -1e30f;
                if (c0 + 1 > qr1) s[nt][3] = -1e30f;
            }
        }

        // ---- online softmax (base-2 domain) ----
        float mt0 = -1e30f, mt1 = -1e30f;
        #pragma unroll
        for (int nt = 0; nt < 8; ++nt) {
            mt0 = fmaxf(mt0, fmaxf(s[nt][0], s[nt][1]));
            mt1 = fmaxf(mt1, fmaxf(s[nt][2], s[nt][3]));
        }
        mt0 = fmaxf(mt0, __shfl_xor_sync(~0u, mt0, 1));
        mt0 = fmaxf(mt0, __shfl_xor_sync(~0u, mt0, 2));
        mt1 = fmaxf(mt1, __shfl_xor_sync(~0u, mt1, 1));
        mt1 = fmaxf(mt1, __shfl_xor_sync(~0u, mt1, 2));
        float mn0 = fmaxf(m0, mt0), mn1 = fmaxf(m1, mt1);
        float c0 = ex2(m0 - mn0), c1 = ex2(m1 - mn1);
        m0 = mn0; m1 = mn1;

        uint32_t phi[16], plo[16];
        float rs0 = 0.f, rs1 = 0.f;
        #pragma unroll
        for (int nt = 0; nt < 8; ++nt) {
            float e0 = ex2(s[nt][0] - mn0), e1 = ex2(s[nt][1] - mn0);
            float e2 = ex2(s[nt][2] - mn1), e3 = ex2(s[nt][3] - mn1);
            rs0 += e0 + e1; rs1 += e2 + e3;
            split_pair(e0, e1, phi[2*nt],     plo[2*nt]);
            split_pair(e2, e3, phi[2*nt + 1], plo[2*nt + 1]);
        }
        rs0 += __shfl_xor_sync(~0u, rs0, 1); rs0 += __shfl_xor_sync(~0u, rs0, 2);
        rs1 += __shfl_xor_sync(~0u, rs1, 1); rs1 += __shfl_xor_sync(~0u, rs1, 2);
        l0 = l0 * c0 + rs0; l1 = l1 * c1 + rs1;

        #pragma unroll
        for (int nt = 0; nt < 8; ++nt) {
            o[nt][0] *= c0; o[nt][1] *= c0;
            o[nt][2] *= c1; o[nt][3] *= c1;
        }

        // ---- O += P V (3 bf16 passes; P frags straight from registers) ----
        #pragma unroll
        for (int ks = 0; ks < 4; ++ks) {
            const uint32_t* ah = phi + 4 * ks;
            const uint32_t* al = plo + 4 * ks;
            #pragma unroll
            for (int p = 0; p < 4; ++p) {
                uint32_t offV = (16u * ks + rowV) * 128u + 32u * p + colV;
                uint32_t bh0, bh1, bh2, bh3, bl0, bl1, bl2, bl3;
                ldsm4t(bh0, bh1, bh2, bh3, ss + VHI + swz(offV));
                ldsm4t(bl0, bl1, bl2, bl3, ss + VLO + swz(offV));
                mma(o[2*p],   ah[0], ah[1], ah[2], ah[3], bh0, bh1);
                mma(o[2*p+1], ah[0], ah[1], ah[2], ah[3], bh2, bh3);
                mma(o[2*p],   al[0], al[1], al[2], al[3], bh0, bh1);
                mma(o[2*p+1], al[0], al[1], al[2], al[3], bh2, bh3);
                mma(o[2*p],   ah[0], ah[1], ah[2], ah[3], bl0, bl1);
                mma(o[2*p+1], ah[0], ah[1], ah[2], ah[3], bl2, bl3);
            }
        }
        __syncthreads();   // stage (kb&1) may be overwritten next iteration
    }

    // ---- epilogue ----
    float rl0 = 1.0f / l0, rl1 = 1.0f / l1;
    #pragma unroll
    for (int nt = 0; nt < 8; ++nt) {
        int col = 8 * nt + 2 * qp;
        *reinterpret_cast<float2*>(Og + (size_t)qr0 * HD + col) =
            make_float2(o[nt][0] * rl0, o[nt][1] * rl0);
        *reinterpret_cast<float2*>(Og + (size_t)qr1 * HD + col) =
            make_float2(o[nt][2] * rl1, o[nt][3] * rl1);
    }
}

} // namespace

extern "C" void kernel_launch(void* const* d_in, const int* in_sizes, int n_in,
                              void* d_out, int out_size)
{
    const float* Q = (const float*)d_in[0];
    const float* K = (const float*)d_in[1];
    const float* V = (const float*)d_in[2];
    float*       O = (float*)d_out;

    split_kv_kernel<<<ELEMS / 4 / 256, 256>>>((const float4*)K, (const float4*)V);

    cudaFuncSetAttribute(fa_hmma_kernel,
                         cudaFuncAttributeMaxDynamicSharedMemorySize, SMEM_BYTES);
    dim3 grid(QT_N, NBH);
    fa_hmma_kernel<<<grid, NTH, SMEM_BYTES>>>(Q, O);
}

// round 6
// speedup vs baseline: 4.6501x; 1.2027x over previous
#include <cuda_runtime.h>
#include <cuda_bf16.h>
#include <cuda_fp16.h>
#include <cstdint>

namespace {

constexpr int SEQ = 2048, HD = 64, BQ = 64, BK = 64, NTH = 128;
constexpr int QT_N  = SEQ / BQ;          // 32 q tiles
constexpr int NBH   = 32;                // B*H
constexpr int ELEMS = NBH * SEQ * HD;    // 4,194,304

// pre-split K (bf16 hi/lo) and V (fp16 hi/lo), packed as x2 words, [bh][s][d]
__device__ uint32_t g_khi[ELEMS / 2];
__device__ uint32_t g_klo[ELEMS / 2];
__device__ uint32_t g_vhi[ELEMS / 2];
__device__ uint32_t g_vlo[ELEMS / 2];

// smem: K ring 2x16KB (hi@+0, lo@+8192), V ring 2x16KB. Q staged in VST[1] pre-loop.
constexpr uint32_t KST0 = 0, KST1 = 16384, VST0 = 32768, VST1 = 49152;
constexpr uint32_t SMEM_BYTES = 65536;   // 3 CTAs/SM

__device__ __forceinline__ uint32_t swz(uint32_t x) { return x ^ ((x >> 3) & 0x70u); }

__device__ __forceinline__ uint32_t s2u(const void* p) {
    uint32_t a;
    asm("{ .reg .u64 t; cvta.to.shared.u64 t, %1; cvt.u32.u64 %0, t; }" : "=r"(a) : "l"(p));
    return a;
}
__device__ __forceinline__ float ex2(float x) {
    float r;
    asm("ex2.approx.ftz.f32 %0, %1;" : "=f"(r) : "f"(x));
    return r;
}
__device__ __forceinline__ void ldsm4(uint32_t& r0, uint32_t& r1, uint32_t& r2, uint32_t& r3,
                                      uint32_t a) {
    asm volatile("ldmatrix.sync.aligned.m8n8.x4.shared.b16 {%0,%1,%2,%3}, [%4];"
                 : "=r"(r0), "=r"(r1), "=r"(r2), "=r"(r3) : "r"(a));
}
__device__ __forceinline__ void ldsm4t(uint32_t& r0, uint32_t& r1, uint32_t& r2, uint32_t& r3,
                                       uint32_t a) {
    asm volatile("ldmatrix.sync.aligned.m8n8.x4.trans.shared.b16 {%0,%1,%2,%3}, [%4];"
                 : "=r"(r0), "=r"(r1), "=r"(r2), "=r"(r3) : "r"(a));
}
__device__ __forceinline__ void mma_bf(float (&d)[4], const uint32_t* a,
                                       const uint32_t b0, const uint32_t b1) {
    asm volatile(
        "mma.sync.aligned.m16n8k16.row.col.f32.bf16.bf16.f32 "
        "{%0,%1,%2,%3}, {%4,%5,%6,%7}, {%8,%9}, {%0,%1,%2,%3};"
        : "+f"(d[0]), "+f"(d[1]), "+f"(d[2]), "+f"(d[3])
        : "r"(a[0]), "r"(a[1]), "r"(a[2]), "r"(a[3]), "r"(b0), "r"(b1));
}
__device__ __forceinline__ void mma_f16(float (&d)[4], const uint32_t* a,
                                        const uint32_t b0, const uint32_t b1) {
    asm volatile(
        "mma.sync.aligned.m16n8k16.row.col.f32.f16.f16.f32 "
        "{%0,%1,%2,%3}, {%4,%5,%6,%7}, {%8,%9}, {%0,%1,%2,%3};"
        : "+f"(d[0]), "+f"(d[1]), "+f"(d[2]), "+f"(d[3])
        : "r"(a[0]), "r"(a[1]), "r"(a[2]), "r"(a[3]), "r"(b0), "r"(b1));
}
// fp32 pair -> packed bf16x2 hi + bf16x2 lo residual
__device__ __forceinline__ void split_pair_bf(float a, float b, uint32_t& hi, uint32_t& lo) {
    __nv_bfloat162 h = __floats2bfloat162_rn(a, b);
    float2 hf = __bfloat1622float2(h);
    __nv_bfloat162 l = __floats2bfloat162_rn(a - hf.x, b - hf.y);
    hi = *reinterpret_cast<uint32_t*>(&h);
    lo = *reinterpret_cast<uint32_t*>(&l);
}
// fp32 pair -> packed fp16x2 hi + fp16x2 lo residual
__device__ __forceinline__ void split_pair_f16(float a, float b, uint32_t& hi, uint32_t& lo) {
    __half2 h = __floats2half2_rn(a, b);
    float2 hf = __half22float2(h);
    __half2 l = __floats2half2_rn(a - hf.x, b - hf.y);
    hi = *reinterpret_cast<uint32_t*>(&h);
    lo = *reinterpret_cast<uint32_t*>(&l);
}
__device__ __forceinline__ void cpa16(uint32_t dst, const void* src) {
    asm volatile("cp.async.cg.shared.global [%0], [%1], 16;" :: "r"(dst), "l"(src) : "memory");
}
#define CP_COMMIT asm volatile("cp.async.commit_group;" ::: "memory")
template <int N>
__device__ __forceinline__ void cp_wait() {
    asm volatile("cp.async.wait_group %0;" :: "n"(N) : "memory");
}

// ---------------- pre-pass: split K (bf16) and V (fp16) hi/lo ----------------
__global__ __launch_bounds__(256)
void split_kv_kernel(const float4* __restrict__ K, const float4* __restrict__ V)
{
    int i = blockIdx.x * 256 + threadIdx.x;
    float4 k = K[i];
    uint32_t h0, l0, h1, l1;
    split_pair_bf(k.x, k.y, h0, l0);
    split_pair_bf(k.z, k.w, h1, l1);
    g_khi[2*i] = h0; g_khi[2*i+1] = h1;
    g_klo[2*i] = l0; g_klo[2*i+1] = l1;
    float4 v = V[i];
    split_pair_f16(v.x, v.y, h0, l0);
    split_pair_f16(v.z, v.w, h1, l1);
    g_vhi[2*i] = h0; g_vhi[2*i+1] = h1;
    g_vlo[2*i] = l0; g_vlo[2*i+1] = l1;
}

// cp.async one 8KB array (64 rows x 128B, swizzled)
__device__ __forceinline__ void issue_arr8k(uint32_t sdst, const char* src, int tid)
{
    #pragma unroll
    for (int t = 0; t < 4; ++t) {
        uint32_t i  = (uint32_t)(t * NTH + tid);
        uint32_t off = (i >> 3) * 128u + (i & 7u) * 16u;
        cpa16(sdst + swz(off), src + off);
    }
}
__device__ __forceinline__ void issue_K(uint32_t slot, int bh, int kb, int tid) {
    size_t boff = (((size_t)bh * SEQ + (size_t)kb * BK) * HD) * 2;
    issue_arr8k(slot,         (const char*)g_khi + boff, tid);
    issue_arr8k(slot + 8192u, (const char*)g_klo + boff, tid);
}
__device__ __forceinline__ void issue_V(uint32_t slot, int bh, int kb, int tid) {
    size_t boff = (((size_t)bh * SEQ + (size_t)kb * BK) * HD) * 2;
    issue_arr8k(slot,         (const char*)g_vhi + boff, tid);
    issue_arr8k(slot + 8192u, (const char*)g_vlo + boff, tid);
}

// interleaved MMA block: S(next) from ssK and/or PV(cur) from ssV
template <bool DO_S, bool DO_PV>
__device__ __forceinline__ void mma_block(
    float (*s)[4], float (*o)[4],
    const uint32_t (*qh)[4], const uint32_t (*ql)[4], const uint32_t* p16,
    uint32_t ssK, uint32_t ssV,
    uint32_t nB, uint32_t kprtB, uint32_t rowV, uint32_t colV)
{
    #pragma unroll
    for (int ks = 0; ks < 4; ++ks) {
        #pragma unroll
        for (int p = 0; p < 4; ++p) {
            uint32_t kh0, kh1, kh2, kh3, kl0, kl1, kl2, kl3;
            uint32_t vh0, vh1, vh2, vh3, vl0, vl1, vl2, vl3;
            if (DO_S) {
                uint32_t offB = (16u * p + nB) * 128u + kprtB + (uint32_t)ks * 32u;
                ldsm4(kh0, kh1, kh2, kh3, ssK + swz(offB));
                ldsm4(kl0, kl1, kl2, kl3, ssK + 8192u + swz(offB));
            }
            if (DO_PV) {
                uint32_t offV = (16u * ks + rowV) * 128u + 32u * p + colV;
                ldsm4t(vh0, vh1, vh2, vh3, ssV + swz(offV));
                ldsm4t(vl0, vl1, vl2, vl3, ssV + 8192u + swz(offV));
            }
            // interleave the two independent streams (reuse distance >= 4)
            if (DO_S) {
                mma_bf(s[2*p],   qh[ks], kh0, kh1);
                mma_bf(s[2*p+1], qh[ks], kh2, kh3);
            }
            if (DO_PV) {
                mma_f16(o[2*p],   p16 + 4*ks, vh0, vh1);
                mma_f16(o[2*p+1], p16 + 4*ks, vh2, vh3);
            }
            if (DO_S) {
                mma_bf(s[2*p],   ql[ks], kh0, kh1);
                mma_bf(s[2*p+1], ql[ks], kh2, kh3);
            }
            if (DO_PV) {
                mma_f16(o[2*p],   p16 + 4*ks, vl0, vl1);
                mma_f16(o[2*p+1], p16 + 4*ks, vl2, vl3);
            }
            if (DO_S) {
                mma_bf(s[2*p],   qh[ks], kl0, kl1);
                mma_bf(s[2*p+1], qh[ks], kl2, kl3);
            }
        }
    }
}

__global__ __launch_bounds__(NTH, 3)
void fa_hmma_kernel(const float* __restrict__ Qg_, float* __restrict__ Og_)
{
    extern __shared__ __align__(1024) char smp[];
    const uint32_t sb = s2u(smp);

    const int tid  = threadIdx.x;
    const int lane = tid & 31, warp = tid >> 5;
    const int quad = lane >> 2, qp = lane & 3;
    const int qt = (QT_N - 1) - (int)blockIdx.x;   // heaviest first
    const int bh = blockIdx.y;

    const float* Qg = Qg_ + ((size_t)bh * SEQ + (size_t)qt * BQ) * HD;
    float*       Og = Og_ + ((size_t)bh * SEQ + (size_t)qt * BQ) * HD;

    const uint32_t rowA  = 16u * warp + (lane & 7) + 8u * ((lane >> 3) & 1);
    const uint32_t kprtA = ((uint32_t)lane >> 4) * 16u;
    const uint32_t nB    = 8u * ((uint32_t)lane >> 4) + (lane & 7);
    const uint32_t kprtB = ((lane >> 3) & 1) * 16u;
    const uint32_t rowV  = (uint32_t)(lane & 15);
    const uint32_t colV  = 16u * ((uint32_t)lane >> 4);

    // ---- stage Q into VST1 region, split, hoist A-fragments ----
    constexpr float QSC = 0.125f * 1.44269504f;
    #pragma unroll
    for (int it = 0; it < 8; ++it) {
        int i = it * NTH + tid;
        int r = i >> 4, dg = i & 15;
        float4 v = reinterpret_cast<const float4*>(Qg)[i];
        uint32_t h0, l0, h1, l1;
        split_pair_bf(v.x * QSC, v.y * QSC, h0, l0);
        split_pair_bf(v.z * QSC, v.w * QSC, h1, l1);
        uint32_t off = (uint32_t)r * 128u + (uint32_t)dg * 8u;
        *(uint32_t*)(smp + VST1 + swz(off))            = h0;
        *(uint32_t*)(smp + VST1 + swz(off + 4))        = h1;
        *(uint32_t*)(smp + VST1 + 8192 + swz(off))     = l0;
        *(uint32_t*)(smp + VST1 + 8192 + swz(off + 4)) = l1;
    }
    __syncthreads();

    uint32_t qh[4][4], ql[4][4];
    #pragma unroll
    for (int ks = 0; ks < 4; ++ks) {
        uint32_t offA = rowA * 128u + kprtA + (uint32_t)ks * 32u;
        ldsm4(qh[ks][0], qh[ks][1], qh[ks][2], qh[ks][3], sb + VST1 + swz(offA));
        ldsm4(ql[ks][0], ql[ks][1], ql[ks][2], ql[ks][3], sb + VST1 + 8192u + swz(offA));
    }
    __syncthreads();   // VST1 free again

    // ---- prime: K0,V0 (g0); K1 (g1, may be empty) ----
    issue_K(sb + KST0, bh, 0, tid);
    issue_V(sb + VST0, bh, 0, tid);
    CP_COMMIT;
    if (qt >= 1) {
        issue_K(sb + KST1, bh, 1, tid);
        CP_COMMIT;
        cp_wait<1>();      // g0 (K0,V0) complete
    } else {
        CP_COMMIT;
        cp_wait<0>();      // qt==0: g1 is empty, must drain g0 fully
    }
    __syncthreads();

    float o[8][4] = {};
    float m0 = -1e30f, m1 = -1e30f, l0 = 0.0f, l1 = 0.0f;
    const int qr0 = 16 * warp + quad, qr1 = qr0 + 8;

    // ---- S(0) ----
    float s[8][4] = {};
    mma_block<true, false>(s, o, qh, ql, nullptr, sb + KST0, 0,
                           nB, kprtB, rowV, colV);

    for (int kb = 0; kb <= qt; ++kb) {
        // ---- causal mask (diagonal tile only) ----
        if (kb == qt) {
            #pragma unroll
            for (int nt = 0; nt < 8; ++nt) {
                int c0 = 8 * nt + 2 * qp;
                if (c0 > qr0)     s[nt][0] = -1e30f;
                if (c0 + 1 > qr0) s[nt][1] = -1e30f;
                if (c0 > qr1)     s[nt][2] = -1e30f;
                if (c0 + 1 > qr1) s[nt][3] = -1e30f;
            }
        }

        // ---- online softmax (base-2 domain) -> P as fp16 ----
        float mt0 = -1e30f, mt1 = -1e30f;
        #pragma unroll
        for (int nt = 0; nt < 8; ++nt) {
            mt0 = fmaxf(mt0, fmaxf(s[nt][0], s[nt][1]));
            mt1 = fmaxf(mt1, fmaxf(s[nt][2], s[nt][3]));
        }
        mt0 = fmaxf(mt0, __shfl_xor_sync(~0u, mt0, 1));
        mt0 = fmaxf(mt0, __shfl_xor_sync(~0u, mt0, 2));
        mt1 = fmaxf(mt1, __shfl_xor_sync(~0u, mt1, 1));
        mt1 = fmaxf(mt1, __shfl_xor_sync(~0u, mt1, 2));
        float mn0 = fmaxf(m0, mt0), mn1 = fmaxf(m1, mt1);
        float c0 = ex2(m0 - mn0), c1 = ex2(m1 - mn1);
        m0 = mn0; m1 = mn1;

        uint32_t p16[16];
        float rs0 = 0.f, rs1 = 0.f;
        #pragma unroll
        for (int nt = 0; nt < 8; ++nt) {
            float e0 = ex2(s[nt][0] - mn0), e1 = ex2(s[nt][1] - mn0);
            float e2 = ex2(s[nt][2] - mn1), e3 = ex2(s[nt][3] - mn1);
            rs0 += e0 + e1; rs1 += e2 + e3;
            __half2 ha = __floats2half2_rn(e0, e1);
            __half2 hb = __floats2half2_rn(e2, e3);
            p16[2*nt]     = *reinterpret_cast<uint32_t*>(&ha);
            p16[2*nt + 1] = *reinterpret_cast<uint32_t*>(&hb);
        }
        rs0 += __shfl_xor_sync(~0u, rs0, 1); rs0 += __shfl_xor_sync(~0u, rs0, 2);
        rs1 += __shfl_xor_sync(~0u, rs1, 1); rs1 += __shfl_xor_sync(~0u, rs1, 2);
        l0 = l0 * c0 + rs0; l1 = l1 * c1 + rs1;
        #pragma unroll
        for (int nt = 0; nt < 8; ++nt) {
            o[nt][0] *= c0; o[nt][1] *= c0;
            o[nt][2] *= c1; o[nt][3] *= c1;
        }

        // ---- prefetch rotation ----
        __syncthreads();   // all warps done reading K(kb) [S done] & V(kb-1) [PV done]
        if (kb < qt) {
            issue_V(sb + (((kb + 1) & 1) ? VST1 : VST0), bh, kb + 1, tid);
            if (kb + 2 <= qt)
                issue_K(sb + ((kb & 1) ? KST1 : KST0), bh, kb + 2, tid);
            CP_COMMIT;
            cp_wait<1>();  // K(kb+1), V(kb) ready
        } else {
            cp_wait<0>();  // V(qt) ready
        }
        __syncthreads();

        // ---- MMA: PV(kb) interleaved with S(kb+1) ----
        const uint32_t ssV = sb + ((kb & 1) ? VST1 : VST0);
        if (kb < qt) {
            const uint32_t ssK = sb + (((kb + 1) & 1) ? KST1 : KST0);
            float sn[8][4] = {};
            mma_block<true, true>(sn, o, qh, ql, p16, ssK, ssV,
                                  nB, kprtB, rowV, colV);
            #pragma unroll
            for (int nt = 0; nt < 8; ++nt) {
                s[nt][0] = sn[nt][0]; s[nt][1] = sn[nt][1];
                s[nt][2] = sn[nt][2]; s[nt][3] = sn[nt][3];
            }
        } else {
            mma_block<false, true>(s, o, qh, ql, p16, 0, ssV,
                                   nB, kprtB, rowV, colV);
        }
    }

    // ---- epilogue ----
    float rl0 = 1.0f / l0, rl1 = 1.0f / l1;
    #pragma unroll
    for (int nt = 0; nt < 8; ++nt) {
        int col = 8 * nt + 2 * qp;
        *reinterpret_cast<float2*>(Og + (size_t)qr0 * HD + col) =
            make_float2(o[nt][0] * rl0, o[nt][1] * rl0);
        *reinterpret_cast<float2*>(Og + (size_t)qr1 * HD + col) =
            make_float2(o[nt][2] * rl1, o[nt][3] * rl1);
    }
}

} // namespace

extern "C" void kernel_launch(void* const* d_in, const int* in_sizes, int n_in,
                              void* d_out, int out_size)
{
    const float* Q = (const float*)d_in[0];
    const float* K = (const float*)d_in[1];
    const float* V = (const float*)d_in[2];
    float*       O = (float*)d_out;

    split_kv_kernel<<<ELEMS / 4 / 256, 256>>>((const float4*)K, (const float4*)V);

    cudaFuncSetAttribute(fa_hmma_kernel,
                         cudaFuncAttributeMaxDynamicSharedMemorySize, SMEM_BYTES);
    dim3 grid(QT_N, NBH);
    fa_hmma_kernel<<<grid, NTH, SMEM_BYTES>>>(Q, O);
}

// round 7
// speedup vs baseline: 8.2853x; 1.7817x over previous
#include <cuda_runtime.h>
#include <cuda_fp16.h>
#include <cstdint>

namespace {

constexpr int SEQ = 2048, HD = 64, BQ = 64, BK = 64, NTH = 128;
constexpr int QT_N  = SEQ / BQ;          // 32 q tiles
constexpr int NBH   = 32;                // B*H
constexpr int ELEMS = NBH * SEQ * HD;    // 4,194,304

// K, V converted to fp16 (packed half2 words), [bh][s][d] order
__device__ uint32_t g_k16[ELEMS / 2];
__device__ uint32_t g_v16[ELEMS / 2];

// smem: K ring 2x8KB, V ring 2x8KB. Q staged in VST1 pre-loop.
constexpr uint32_t KST0 = 0, KST1 = 8192, VST0 = 16384, VST1 = 24576;
constexpr uint32_t SMEM_BYTES = 32768;   // 4 CTAs/SM (128KB)

__device__ __forceinline__ uint32_t swz(uint32_t x) { return x ^ ((x >> 3) & 0x70u); }

__device__ __forceinline__ uint32_t s2u(const void* p) {
    uint32_t a;
    asm("{ .reg .u64 t; cvta.to.shared.u64 t, %1; cvt.u32.u64 %0, t; }" : "=r"(a) : "l"(p));
    return a;
}
__device__ __forceinline__ float ex2(float x) {
    float r;
    asm("ex2.approx.ftz.f32 %0, %1;" : "=f"(r) : "f"(x));
    return r;
}
__device__ __forceinline__ void ldsm4(uint32_t& r0, uint32_t& r1, uint32_t& r2, uint32_t& r3,
                                      uint32_t a) {
    asm volatile("ldmatrix.sync.aligned.m8n8.x4.shared.b16 {%0,%1,%2,%3}, [%4];"
                 : "=r"(r0), "=r"(r1), "=r"(r2), "=r"(r3) : "r"(a));
}
__device__ __forceinline__ void ldsm4t(uint32_t& r0, uint32_t& r1, uint32_t& r2, uint32_t& r3,
                                       uint32_t a) {
    asm volatile("ldmatrix.sync.aligned.m8n8.x4.trans.shared.b16 {%0,%1,%2,%3}, [%4];"
                 : "=r"(r0), "=r"(r1), "=r"(r2), "=r"(r3) : "r"(a));
}
__device__ __forceinline__ void mma_f16(float (&d)[4], const uint32_t* a,
                                        const uint32_t b0, const uint32_t b1) {
    asm volatile(
        "mma.sync.aligned.m16n8k16.row.col.f32.f16.f16.f32 "
        "{%0,%1,%2,%3}, {%4,%5,%6,%7}, {%8,%9}, {%0,%1,%2,%3};"
        : "+f"(d[0]), "+f"(d[1]), "+f"(d[2]), "+f"(d[3])
        : "r"(a[0]), "r"(a[1]), "r"(a[2]), "r"(a[3]), "r"(b0), "r"(b1));
}
__device__ __forceinline__ void cpa16(uint32_t dst, const void* src) {
    asm volatile("cp.async.cg.shared.global [%0], [%1], 16;" :: "r"(dst), "l"(src) : "memory");
}
#define CP_COMMIT asm volatile("cp.async.commit_group;" ::: "memory")
template <int N>
__device__ __forceinline__ void cp_wait() {
    asm volatile("cp.async.wait_group %0;" :: "n"(N) : "memory");
}

// ---------------- pre-pass: convert K,V to fp16 ----------------
__global__ __launch_bounds__(256)
void cvt_kv_kernel(const float4* __restrict__ K, const float4* __restrict__ V)
{
    int i = blockIdx.x * 256 + threadIdx.x;
    float4 k = K[i];
    __half2 a = __floats2half2_rn(k.x, k.y);
    __half2 b = __floats2half2_rn(k.z, k.w);
    g_k16[2*i]   = *reinterpret_cast<uint32_t*>(&a);
    g_k16[2*i+1] = *reinterpret_cast<uint32_t*>(&b);
    float4 v = V[i];
    a = __floats2half2_rn(v.x, v.y);
    b = __floats2half2_rn(v.z, v.w);
    g_v16[2*i]   = *reinterpret_cast<uint32_t*>(&a);
    g_v16[2*i+1] = *reinterpret_cast<uint32_t*>(&b);
}

// cp.async one 8KB tile (64 rows x 128B, swizzled)
__device__ __forceinline__ void issue_tile8k(uint32_t sdst, const uint32_t* garr,
                                             int bh, int kb, int tid)
{
    const char* src = (const char*)garr + (((size_t)bh * SEQ + (size_t)kb * BK) * HD) * 2;
    #pragma unroll
    for (int t = 0; t < 4; ++t) {
        uint32_t i  = (uint32_t)(t * NTH + tid);
        uint32_t off = (i >> 3) * 128u + (i & 7u) * 16u;
        cpa16(sdst + swz(off), src + off);
    }
}

// interleaved MMA block: S(next) = Q K^T from ssK and/or O += P V from ssV
template <bool DO_S, bool DO_PV>
__device__ __forceinline__ void mma_block(
    float (*s)[4], float (*o)[4],
    const uint32_t (*qf)[4], const uint32_t* p16,
    uint32_t ssK, uint32_t ssV,
    uint32_t nB, uint32_t kprtB, uint32_t rowV, uint32_t colV)
{
    #pragma unroll
    for (int ks = 0; ks < 4; ++ks) {
        #pragma unroll
        for (int p = 0; p < 4; ++p) {
            uint32_t k0, k1, k2, k3, v0, v1, v2, v3;
            if (DO_S) {
                uint32_t offB = (16u * p + nB) * 128u + kprtB + (uint32_t)ks * 32u;
                ldsm4(k0, k1, k2, k3, ssK + swz(offB));
            }
            if (DO_PV) {
                uint32_t offV = (16u * ks + rowV) * 128u + 32u * p + colV;
                ldsm4t(v0, v1, v2, v3, ssV + swz(offV));
            }
            if (DO_S) {
                mma_f16(s[2*p],   qf[ks], k0, k1);
                mma_f16(s[2*p+1], qf[ks], k2, k3);
            }
            if (DO_PV) {
                mma_f16(o[2*p],   p16 + 4*ks, v0, v1);
                mma_f16(o[2*p+1], p16 + 4*ks, v2, v3);
            }
        }
    }
}

__global__ __launch_bounds__(NTH, 4)
void fa_hmma_kernel(const float* __restrict__ Qg_, float* __restrict__ Og_)
{
    extern __shared__ __align__(1024) char smp[];
    const uint32_t sb = s2u(smp);

    const int tid  = threadIdx.x;
    const int lane = tid & 31, warp = tid >> 5;
    const int quad = lane >> 2, qp = lane & 3;
    const int qt = (QT_N - 1) - (int)blockIdx.x;   // heaviest first
    const int bh = blockIdx.y;

    const float* Qg = Qg_ + ((size_t)bh * SEQ + (size_t)qt * BQ) * HD;
    float*       Og = Og_ + ((size_t)bh * SEQ + (size_t)qt * BQ) * HD;

    const uint32_t rowA  = 16u * warp + (lane & 7) + 8u * ((lane >> 3) & 1);
    const uint32_t kprtA = ((uint32_t)lane >> 4) * 16u;
    const uint32_t nB    = 8u * ((uint32_t)lane >> 4) + (lane & 7);
    const uint32_t kprtB = ((lane >> 3) & 1) * 16u;
    const uint32_t rowV  = (uint32_t)(lane & 15);
    const uint32_t colV  = 16u * ((uint32_t)lane >> 4);

    // ---- stage Q (fp16, scale*log2e folded) into VST1, hoist A-fragments ----
    constexpr float QSC = 0.125f * 1.44269504f;
    #pragma unroll
    for (int it = 0; it < 8; ++it) {
        int i = it * NTH + tid;         // i indexes float4 groups: row = i>>4, dgrp = i&15
        int r = i >> 4, dg = i & 15;
        float4 v = reinterpret_cast<const float4*>(Qg)[i];
        __half2 a = __floats2half2_rn(v.x * QSC, v.y * QSC);
        __half2 b = __floats2half2_rn(v.z * QSC, v.w * QSC);
        uint32_t off = (uint32_t)r * 128u + (uint32_t)dg * 8u;
        *(uint32_t*)(smp + VST1 + swz(off))     = *reinterpret_cast<uint32_t*>(&a);
        *(uint32_t*)(smp + VST1 + swz(off + 4)) = *reinterpret_cast<uint32_t*>(&b);
    }
    __syncthreads();

    uint32_t qf[4][4];
    #pragma unroll
    for (int ks = 0; ks < 4; ++ks) {
        uint32_t offA = rowA * 128u + kprtA + (uint32_t)ks * 32u;
        ldsm4(qf[ks][0], qf[ks][1], qf[ks][2], qf[ks][3], sb + VST1 + swz(offA));
    }
    __syncthreads();   // VST1 free again

    // ---- prime: K0,V0 (g0); K1 (g1, may be absent) ----
    issue_tile8k(sb + KST0, g_k16, bh, 0, tid);
    issue_tile8k(sb + VST0, g_v16, bh, 0, tid);
    CP_COMMIT;
    if (qt >= 1) {
        issue_tile8k(sb + KST1, g_k16, bh, 1, tid);
        CP_COMMIT;
        cp_wait<1>();      // K0,V0 ready
    } else {
        CP_COMMIT;
        cp_wait<0>();
    }
    __syncthreads();

    float o[8][4] = {};
    float m0 = -1e30f, m1 = -1e30f, l0 = 0.0f, l1 = 0.0f;
    const int qr0 = 16 * warp + quad, qr1 = qr0 + 8;

    // ---- S(0) ----
    float s[8][4] = {};
    mma_block<true, false>(s, o, qf, nullptr, sb + KST0, 0, nB, kprtB, rowV, colV);

    for (int kb = 0; kb <= qt; ++kb) {
        // ---- causal mask (diagonal tile only) ----
        if (kb == qt) {
            #pragma unroll
            for (int nt = 0; nt < 8; ++nt) {
                int c0 = 8 * nt + 2 * qp;
                if (c0 > qr0)     s[nt][0] = -1e30f;
                if (c0 + 1 > qr0) s[nt][1] = -1e30f;
                if (c0 > qr1)     s[nt][2] = -1e30f;
                if (c0 + 1 > qr1) s[nt][3] = -1e30f;
            }
        }

        // ---- online softmax (base-2 domain) -> P as fp16 ----
        float mt0 = -1e30f, mt1 = -1e30f;
        #pragma unroll
        for (int nt = 0; nt < 8; ++nt) {
            mt0 = fmaxf(mt0, fmaxf(s[nt][0], s[nt][1]));
            mt1 = fmaxf(mt1, fmaxf(s[nt][2], s[nt][3]));
        }
        mt0 = fmaxf(mt0, __shfl_xor_sync(~0u, mt0, 1));
        mt0 = fmaxf(mt0, __shfl_xor_sync(~0u, mt0, 2));
        mt1 = fmaxf(mt1, __shfl_xor_sync(~0u, mt1, 1));
        mt1 = fmaxf(mt1, __shfl_xor_sync(~0u, mt1, 2));
        float mn0 = fmaxf(m0, mt0), mn1 = fmaxf(m1, mt1);
        float c0 = ex2(m0 - mn0), c1 = ex2(m1 - mn1);
        m0 = mn0; m1 = mn1;

        uint32_t p16[16];
        float rs0 = 0.f, rs1 = 0.f;
        #pragma unroll
        for (int nt = 0; nt < 8; ++nt) {
            float e0 = ex2(s[nt][0] - mn0), e1 = ex2(s[nt][1] - mn0);
            float e2 = ex2(s[nt][2] - mn1), e3 = ex2(s[nt][3] - mn1);
            rs0 += e0 + e1; rs1 += e2 + e3;
            __half2 ha = __floats2half2_rn(e0, e1);
            __half2 hb = __floats2half2_rn(e2, e3);
            p16[2*nt]     = *reinterpret_cast<uint32_t*>(&ha);
            p16[2*nt + 1] = *reinterpret_cast<uint32_t*>(&hb);
        }
        rs0 += __shfl_xor_sync(~0u, rs0, 1); rs0 += __shfl_xor_sync(~0u, rs0, 2);
        rs1 += __shfl_xor_sync(~0u, rs1, 1); rs1 += __shfl_xor_sync(~0u, rs1, 2);
        l0 = l0 * c0 + rs0; l1 = l1 * c1 + rs1;
        #pragma unroll
        for (int nt = 0; nt < 8; ++nt) {
            o[nt][0] *= c0; o[nt][1] *= c0;
            o[nt][2] *= c1; o[nt][3] *= c1;
        }

        // ---- prefetch rotation ----
        __syncthreads();   // all warps done reading K(kb) [S] & V(kb-1) [PV]
        if (kb < qt) {
            issue_tile8k(sb + (((kb + 1) & 1) ? VST1 : VST0), g_v16, bh, kb + 1, tid);
            if (kb + 2 <= qt)
                issue_tile8k(sb + ((kb & 1) ? KST1 : KST0), g_k16, bh, kb + 2, tid);
            CP_COMMIT;
            cp_wait<1>();  // K(kb+1), V(kb) ready
        } else {
            cp_wait<0>();  // V(qt) ready
        }
        __syncthreads();

        // ---- MMA: PV(kb) interleaved with S(kb+1); s is dead, reuse in place ----
        const uint32_t ssV = sb + ((kb & 1) ? VST1 : VST0);
        if (kb < qt) {
            #pragma unroll
            for (int nt = 0; nt < 8; ++nt) {
                s[nt][0] = 0.f; s[nt][1] = 0.f; s[nt][2] = 0.f; s[nt][3] = 0.f;
            }
            const uint32_t ssK = sb + (((kb + 1) & 1) ? KST1 : KST0);
            mma_block<true, true>(s, o, qf, p16, ssK, ssV, nB, kprtB, rowV, colV);
        } else {
            mma_block<false, true>(s, o, qf, p16, 0, ssV, nB, kprtB, rowV, colV);
        }
    }

    // ---- epilogue ----
    float rl0 = 1.0f / l0, rl1 = 1.0f / l1;
    #pragma unroll
    for (int nt = 0; nt < 8; ++nt) {
        int col = 8 * nt + 2 * qp;
        *reinterpret_cast<float2*>(Og + (size_t)qr0 * HD + col) =
            make_float2(o[nt][0] * rl0, o[nt][1] * rl0);
        *reinterpret_cast<float2*>(Og + (size_t)qr1 * HD + col) =
            make_float2(o[nt][2] * rl1, o[nt][3] * rl1);
    }
}

} // namespace

extern "C" void kernel_launch(void* const* d_in, const int* in_sizes, int n_in,
                              void* d_out, int out_size)
{
    const float* Q = (const float*)d_in[0];
    const float* K = (const float*)d_in[1];
    const float* V = (const float*)d_in[2];
    float*       O = (float*)d_out;

    cvt_kv_kernel<<<ELEMS / 4 / 256, 256>>>((const float4*)K, (const float4*)V);

    cudaFuncSetAttribute(fa_hmma_kernel,
                         cudaFuncAttributeMaxDynamicSharedMemorySize, SMEM_BYTES);
    dim3 grid(QT_N, NBH);
    fa_hmma_kernel<<<grid, NTH, SMEM_BYTES>>>(Q, O);
}